// round 6
// baseline (speedup 1.0000x reference)
#include <cuda_runtime.h>

// Problem constants
#define EE   130
#define HH   8
#define NTOK 32768                  // B*N
#define ROWF 1040                   // H*E
#define SEGF ((size_t)NTOK * ROWF)  // floats per output tensor (q|k|v)

#define THREADS 512
#define M_TILE  64
#define BLOCKS  (NTOK / M_TILE)     // 512

// smem layout (floats); stride 68: row byte-stride 272 = 16B-aligned for
// LDS.128, and 68*row mod 32 = 4*row mod 32 spreads each 8-lane phase
// across disjoint bank quads -> conflict-free 128-bit loads.
#define XST 68
#define SX1_OFF   0                         // 64 x 68
#define SX2_OFF   (SX1_OFF + 64 * XST)      // 64 x 68
#define SMID_OFF  (SX2_OFF + 64 * XST)      // 64
#define SLAST_OFF (SMID_OFF + 64)           // 64
#define W_OFF     (SLAST_OFF + 64)          // 2 x (64 x 68) double buffer
#define WBUF      (64 * XST)
#define SMEM_FLOATS (W_OFF + 2 * WBUF)      // 17536 floats = 70144 B

typedef unsigned long long ull;

// Packed f32x2 FMA (sm_100+ FFMA2): d = a*b + c lane-wise on two packed floats.
__device__ __forceinline__ ull ffma2(ull a, ull b, ull c) {
    ull d;
    asm("fma.rn.f32x2 %0, %1, %2, %3;" : "=l"(d) : "l"(a), "l"(b), "l"(c));
    return d;
}
__device__ __forceinline__ float hadd2(ull a) {
    float lo, hi;
    asm("mov.b64 {%0, %1}, %2;" : "=f"(lo), "=f"(hi) : "l"(a));
    return lo + hi;
}

__global__ __launch_bounds__(THREADS, 2) void fused_qkv_kernel(
    const float* __restrict__ x,
    const float* __restrict__ Mq,
    const float* __restrict__ Bq,
    const float* __restrict__ Mk,
    const float* __restrict__ Bk,
    const float* __restrict__ Mv,
    float* __restrict__ out)
{
    extern __shared__ float sm[];
    float* sx1   = sm + SX1_OFF;    // x[:, 0:64)   token-major, stride 68
    float* sx2   = sm + SX2_OFF;    // x[:, 65:129) remapped to 0..63
    float* smid  = sm + SMID_OFF;   // x[:, 64]
    float* slast = sm + SLAST_OFF;  // x[:, 129]

    const int tid  = threadIdx.x;
    const int warp = tid >> 5;      // 0..15
    const int lane = tid & 31;
    const int tx   = tid & 15;      // output group: oi in {tx, tx+16, tx+32, tx+48}
    const int ty   = tid >> 4;      // token  group: ti in {ty, ty+32}
    const int t0   = blockIdx.x * M_TILE;

    // matvec schedule: mi 0..3 = M_k (x1,seg1), 4..11 = M_v (x1,seg2), 12..15 = M_q (x2,seg0)
    auto wsrc_of = [&](int mi) -> const float* {
        if (mi < 4)  return Mk + mi * 4096;
        if (mi < 12) return Mv + (mi - 4) * 4096;
        return Mq + (mi - 12) * 4096;
    };

    // ---- prefetch weight matrix 0 into registers (2 float4 per thread) ----
    float4 wpre[2];
    {
        const float4* w4 = reinterpret_cast<const float4*>(wsrc_of(0));
        #pragma unroll
        for (int r = 0; r < 2; ++r) wpre[r] = __ldg(w4 + tid + r * THREADS);
    }

    // ---- stage this block's 64 tokens of x into split smem ----
    {
        const float* xg = x + (size_t)t0 * EE;          // contiguous 8320 floats
        for (int idx = tid; idx < M_TILE * EE; idx += THREADS) {
            int t = idx / EE;
            int e = idx - t * EE;
            float v = __ldg(xg + idx);
            if (e < 64)        sx1[t * XST + e] = v;
            else if (e == 64)  smid[t] = v;
            else if (e < 129)  sx2[t * XST + (e - 65)] = v;
            else               slast[t] = v;
        }
    }

    // ---- store prefetched matrix 0 into weight buffer 0 (stride 68) ----
    {
        float* ws = sm + W_OFF;
        #pragma unroll
        for (int r = 0; r < 2; ++r) {
            int l = (tid + r * THREADS) * 4;            // linear float idx in 64x64
            int row = l >> 6, col = l & 63;
            *(float4*)(ws + row * XST + col) = wpre[r]; // 16B aligned (272*row + 4*col)
        }
    }
    __syncthreads();    // x staging + weight buffer 0 visible to all

    // ------------------------------------------------------------------
    // Zero-fill + biases, warp-per-row (coalesced 256B stores).
    //   class A (v any h; q/k h<4): zero [0,65), col129 = 0 (v) or bias (q/k);
    //                               [65,129) written by matvec below.
    //   class B (q/k h>=4):         zero [0,130) except col65 = bias.
    // ------------------------------------------------------------------
    {
        const float2 z2 = make_float2(0.f, 0.f);
        for (int rid = warp; rid < M_TILE * 24; rid += 16) {
            int t   = rid / 24;
            int r   = rid - t * 24;
            int seg = r >> 3, h = r & 7;
            float* p = out + (size_t)seg * SEGF + (size_t)(t0 + t) * ROWF + h * EE;

            *(float2*)(p + 2 * lane) = z2;              // cols [0,64)

            if (seg == 2 || h < 4) {                    // class A
                if (lane == 0) p[64] = 0.f;
                if (lane == 1) {
                    float v129 = 0.f;
                    if (seg == 0)      v129 = slast[t] * __ldg(Bq + h);
                    else if (seg == 1) v129 = slast[t] * __ldg(Bk + h);
                    p[129] = v129;
                }
            } else {                                    // class B: q/k h>=4
                float2 v = z2;
                if (lane == 0) {
                    float b = (seg == 0) ? __ldg(Bq + h) : __ldg(Bk + h);
                    v.y = ((seg == 0) ? slast[t] : smid[t]) * b;
                }
                *(float2*)(p + 64 + 2 * lane) = v;      // cols [64,128)
                if (lane == 0) *(float2*)(p + 128) = z2;
            }
        }
    }

    // ---- 16 matvec tiles, double-buffered weights, fully unrolled k ----
    for (int mi = 0; mi < 16; ++mi) {
        if (mi + 1 < 16) {
            const float4* w4 = reinterpret_cast<const float4*>(wsrc_of(mi + 1));
            #pragma unroll
            for (int r = 0; r < 2; ++r) wpre[r] = __ldg(w4 + tid + r * THREADS);
        }

        const float* ws = sm + W_OFF + (mi & 1) * WBUF;
        const float* xs = (mi < 12) ? sx1 : sx2;

        // 128-bit smem base pointers (all 16B aligned)
        const ulonglong2* xr0 = (const ulonglong2*)(xs + (size_t)ty * XST);
        const ulonglong2* xr1 = (const ulonglong2*)(xs + (size_t)(ty + 32) * XST);
        const ulonglong2* wr0 = (const ulonglong2*)(ws + (size_t)tx * XST);
        const ulonglong2* wr1 = (const ulonglong2*)(ws + (size_t)(tx + 16) * XST);
        const ulonglong2* wr2 = (const ulonglong2*)(ws + (size_t)(tx + 32) * XST);
        const ulonglong2* wr3 = (const ulonglong2*)(ws + (size_t)(tx + 48) * XST);

        ull acc[2][4];
        #pragma unroll
        for (int i = 0; i < 2; ++i)
            #pragma unroll
            for (int o = 0; o < 4; ++o) acc[i][o] = 0ULL;

        #pragma unroll
        for (int s = 0; s < 16; ++s) {                  // 4 floats (2 jp) per step
            ulonglong2 xa = xr0[s];                     // broadcast (half-warp uniform)
            ulonglong2 xb = xr1[s];
            ulonglong2 w0 = wr0[s];                     // 16 distinct rows, conflict-free
            ulonglong2 w1 = wr1[s];
            ulonglong2 w2 = wr2[s];
            ulonglong2 w3 = wr3[s];
            acc[0][0] = ffma2(w0.x, xa.x, acc[0][0]);
            acc[0][1] = ffma2(w1.x, xa.x, acc[0][1]);
            acc[0][2] = ffma2(w2.x, xa.x, acc[0][2]);
            acc[0][3] = ffma2(w3.x, xa.x, acc[0][3]);
            acc[1][0] = ffma2(w0.x, xb.x, acc[1][0]);
            acc[1][1] = ffma2(w1.x, xb.x, acc[1][1]);
            acc[1][2] = ffma2(w2.x, xb.x, acc[1][2]);
            acc[1][3] = ffma2(w3.x, xb.x, acc[1][3]);
            acc[0][0] = ffma2(w0.y, xa.y, acc[0][0]);
            acc[0][1] = ffma2(w1.y, xa.y, acc[0][1]);
            acc[0][2] = ffma2(w2.y, xa.y, acc[0][2]);
            acc[0][3] = ffma2(w3.y, xa.y, acc[0][3]);
            acc[1][0] = ffma2(w0.y, xb.y, acc[1][0]);
            acc[1][1] = ffma2(w1.y, xb.y, acc[1][1]);
            acc[1][2] = ffma2(w2.y, xb.y, acc[1][2]);
            acc[1][3] = ffma2(w3.y, xb.y, acc[1][3]);
        }

        size_t obase; int h;
        if (mi < 4)       { obase = SEGF;     h = mi; }
        else if (mi < 12) { obase = 2 * SEGF; h = mi - 4; }
        else              { obase = 0;        h = mi - 12; }

        #pragma unroll
        for (int i = 0; i < 2; ++i) {
            float* dst = out + obase + (size_t)(t0 + ty + 32 * i) * ROWF + h * EE + 65;
            #pragma unroll
            for (int o = 0; o < 4; ++o)
                dst[tx + 16 * o] = hadd2(acc[i][o]);    // half-warp: 16 consecutive floats
        }

        if (mi + 1 < 16) {
            float* wd = sm + W_OFF + ((mi + 1) & 1) * WBUF;
            #pragma unroll
            for (int r = 0; r < 2; ++r) {
                int l = (tid + r * THREADS) * 4;
                int row = l >> 6, col = l & 63;
                *(float4*)(wd + row * XST + col) = wpre[r];
            }
            __syncthreads();    // publishes wbuf(mi+1), protects wbuf(mi) reuse
        }
    }
}

extern "C" void kernel_launch(void* const* d_in, const int* in_sizes, int n_in,
                              void* d_out, int out_size) {
    const float* x  = (const float*)d_in[0];
    const float* Mq = (const float*)d_in[1];
    const float* Bq = (const float*)d_in[2];
    const float* Mk = (const float*)d_in[3];
    const float* Bk = (const float*)d_in[4];
    const float* Mv = (const float*)d_in[5];
    float* out = (float*)d_out;

    const size_t smem = SMEM_FLOATS * sizeof(float);    // 70144 B
    cudaFuncSetAttribute(fused_qkv_kernel,
                         cudaFuncAttributeMaxDynamicSharedMemorySize, (int)smem);
    fused_qkv_kernel<<<BLOCKS, THREADS, smem>>>(x, Mq, Bq, Mk, Bk, Mv, out);
}